// round 15
// baseline (speedup 1.0000x reference)
#include <cuda_runtime.h>
#include <cuda_fp16.h>
#include <math.h>
#include <stdint.h>

typedef __half h16;

// B=4, T=2048, D=512, H=8, HD=64, F=2048, WINDOW=128, rows=8192

// ---------------- scratch ----------------
__device__ h16  g_q  [32 * 2048 * 64];   // [bh][t][d], scaled
__device__ h16  g_k  [32 * 2048 * 64];   // [bh][t][d]
__device__ h16  g_vt [32 * 64 * 2048];   // [bh][d][t]
__device__ h16  g_x2 [8192 * 512];
__device__ h16  g_ctx[8192 * 512];
__device__ h16  g_x3 [8192 * 512];
__device__ h16  g_h  [8192 * 2048];
__device__ h16  g_wa [1536 * 512];
__device__ h16  g_wb [512 * 512];
__device__ h16  g_w1 [2048 * 512];
__device__ h16  g_w2 [512 * 2048];

// ---------------- helpers ----------------
__device__ __forceinline__ uint32_t smem_u32(const void* p) {
    uint32_t a;
    asm("{ .reg .u64 t; cvta.to.shared.u64 t, %1; cvt.u32.u64 %0, t; }" : "=r"(a) : "l"(p));
    return a;
}
__device__ __forceinline__ void cp16(uint32_t d, const void* g) {
    asm volatile("cp.async.cg.shared.global [%0], [%1], 16;" :: "r"(d), "l"(g));
}
__device__ __forceinline__ void cp16z(uint32_t d, const void* g, uint32_t srcsz) {
    asm volatile("cp.async.cg.shared.global [%0], [%1], 16, %2;" :: "r"(d), "l"(g), "r"(srcsz));
}
#define CP_COMMIT() asm volatile("cp.async.commit_group;" ::: "memory")
#define CP_WAIT(n)  asm volatile("cp.async.wait_group %0;" :: "n"(n) : "memory")

#define LDSM4(r, addr) \
    asm volatile("ldmatrix.sync.aligned.m8n8.x4.shared.b16 {%0,%1,%2,%3}, [%4];" \
        : "=r"((r)[0]), "=r"((r)[1]), "=r"((r)[2]), "=r"((r)[3]) : "r"(addr))

#define MMA16816(c, a, b) \
    asm volatile("mma.sync.aligned.m16n8k16.row.col.f32.f16.f16.f32 " \
        "{%0,%1,%2,%3}, {%4,%5,%6,%7}, {%8,%9}, {%0,%1,%2,%3};" \
        : "+f"((c)[0]), "+f"((c)[1]), "+f"((c)[2]), "+f"((c)[3]) \
        : "r"((a)[0]), "r"((a)[1]), "r"((a)[2]), "r"((a)[3]), "r"((b)[0]), "r"((b)[1]))

__device__ __forceinline__ void cvtH2(float a, float b, h16* p) {
    *(__half2*)p = __halves2half2(__float2half_rn(a), __float2half_rn(b));
}

// ---------------- fused weight convert ----------------
__global__ void split_all_kernel(const float* __restrict__ in_w, const float* __restrict__ out_w,
                                 const float* __restrict__ w1, const float* __restrict__ w2,
                                 h16* __restrict__ wa, h16* __restrict__ wb,
                                 h16* __restrict__ w1o, h16* __restrict__ w2o) {
    int i = blockIdx.x * 256 + threadIdx.x;   // unit = 4 floats; total 786432
    const float* src; h16* dst; int off;
    if (i < 196608)      { src = in_w;  dst = wa;  off = i; }
    else if (i < 262144) { src = out_w; dst = wb;  off = i - 196608; }
    else if (i < 524288) { src = w1;    dst = w1o; off = i - 262144; }
    else                 { src = w2;    dst = w2o; off = i - 524288; }
    float4 v = *(const float4*)(src + (size_t)off * 4);
    cvtH2(v.x, v.y, dst + (size_t)off * 4);
    cvtH2(v.z, v.w, dst + (size_t)off * 4 + 2);
}

// ---------------- LayerNorm -> single fp16 ----------------
__global__ void ln_h_kernel(const float* __restrict__ x, const float* __restrict__ gw,
                            const float* __restrict__ bw, h16* __restrict__ o) {
    int row = blockIdx.x;
    int t = threadIdx.x;
    const float* xr = x + (size_t)row * 512;
    float4 v = *(const float4*)(xr + t * 4);
    float s  = v.x + v.y + v.z + v.w;
    float sq = v.x * v.x + v.y * v.y + v.z * v.z + v.w * v.w;
    #pragma unroll
    for (int of = 16; of > 0; of >>= 1) {
        s  += __shfl_xor_sync(0xffffffffu, s,  of);
        sq += __shfl_xor_sync(0xffffffffu, sq, of);
    }
    __shared__ float red[8];
    int wid = t >> 5, lane = t & 31;
    if (lane == 0) { red[wid] = s; red[4 + wid] = sq; }
    __syncthreads();
    float S  = red[0] + red[1] + red[2] + red[3];
    float SQ = red[4] + red[5] + red[6] + red[7];
    float mu   = S * (1.0f / 512.0f);
    float var  = SQ * (1.0f / 512.0f) - mu * mu;
    float rstd = rsqrtf(var + 1e-5f);
    float4 gv = *(const float4*)(gw + t * 4);
    float4 bv = *(const float4*)(bw + t * 4);
    float o0 = (v.x - mu) * rstd * gv.x + bv.x;
    float o1 = (v.y - mu) * rstd * gv.y + bv.y;
    float o2 = (v.z - mu) * rstd * gv.z + bv.z;
    float o3 = (v.w - mu) * rstd * gv.w + bv.w;
    size_t base = (size_t)row * 512 + t * 4;
    cvtH2(o0, o1, o + base);
    cvtH2(o2, o3, o + base + 2);
}

// ---------------- mma.sync GEMM: C = A @ W^T, single fp16 ----------------
// CTA 128x128, 256 threads, 8 warps of 64x32 (2m x 4n), BK=32, 4-stage cp.async.
// 64KB smem, ~110 regs -> 2 CTAs/SM = 16 warps/SM (4 per SMSP).
#define EPI_BIAS_RES   1
#define EPI_GELU       2
#define EPI_QKV        3

#define TILE_B   8192            // 128 rows x 64 B
#define STAGE_B  (2 * TILE_B)    // 16384 (A, W)
#define NSTAGE   4
#define GEMM_SMEM (NSTAGE * STAGE_B)   // 65536

#define SWIZ(row, chunk) ((row) * 64 + (((chunk) ^ (((row) >> 1) & 3)) << 4))

template<int EPI>
__global__ __launch_bounds__(256, 2)
void gemm_mma(const h16* __restrict__ A, const h16* __restrict__ W,
              const float* __restrict__ bias, const float* __restrict__ res,
              float* __restrict__ Cf, h16* __restrict__ Ch,
              h16* __restrict__ Kh, h16* __restrict__ Vth,
              int N, int K) {
    extern __shared__ char sm[];
    const int tid = threadIdx.x;
    const int lane = tid & 31, wid = tid >> 5;
    const int wm = wid & 1, wn = wid >> 1;          // 2 x 4 warp grid, warp tile 64x32
    const int m0 = blockIdx.y * 128, n0 = blockIdx.x * 128;
    const uint32_t sbase = smem_u32(sm);

    const h16* srcs[2] = { A + (size_t)m0 * K, W + (size_t)n0 * K };

    auto load_stage = [&](int s, int kb) {
        uint32_t so = sbase + (uint32_t)s * STAGE_B;
        #pragma unroll
        for (int tt = 0; tt < 2; tt++) {
            const h16* gp = srcs[tt] + kb * 32;
            uint32_t tb = so + tt * TILE_B;
            #pragma unroll
            for (int it = 0; it < 2; it++) {
                int idx = tid + it * 256;          // 0..511
                int r = idx >> 2, c = idx & 3;
                cp16(tb + SWIZ(r, c), gp + (size_t)r * K + c * 8);
            }
        }
    };

    float acc[4][4][4];
    #pragma unroll
    for (int i = 0; i < 4; i++)
        #pragma unroll
        for (int j = 0; j < 4; j++)
            #pragma unroll
            for (int r = 0; r < 4; r++) acc[i][j][r] = 0.0f;

    const int nkb = K >> 5;

    load_stage(0, 0); CP_COMMIT();
    load_stage(1, 1); CP_COMMIT();
    load_stage(2, 2); CP_COMMIT();

    const uint32_t aRow = wm * 64 + (lane & 15);
    const uint32_t aChunkHalf = (lane >> 4);
    const uint32_t bRow = wn * 32 + (lane & 7) + ((lane >> 4) << 3);
    const uint32_t bChunkHalf = (lane >> 3) & 1;

    for (int kb = 0; kb < nkb; kb++) {
        bool more = (kb + NSTAGE - 1) < nkb;
        if (more) { CP_WAIT(NSTAGE - 2); } else { CP_WAIT(0); }
        __syncthreads();
        if (more) { load_stage((kb + NSTAGE - 1) % NSTAGE, kb + NSTAGE - 1); CP_COMMIT(); }

        uint32_t so = sbase + (uint32_t)(kb % NSTAGE) * STAGE_B;
        #pragma unroll
        for (int ks = 0; ks < 2; ks++) {
            const uint32_t kcA = ks * 2 + aChunkHalf;
            const uint32_t kcB = ks * 2 + bChunkHalf;
            uint32_t Af[4][4];
            #pragma unroll
            for (int i = 0; i < 4; i++)
                LDSM4(Af[i], so + SWIZ(aRow + i * 16, kcA));
            uint32_t Wf[2][4];
            #pragma unroll
            for (int jp = 0; jp < 2; jp++)
                LDSM4(Wf[jp], so + TILE_B + SWIZ(bRow + jp * 16, kcB));
            #pragma unroll
            for (int i = 0; i < 4; i++) {
                #pragma unroll
                for (int j = 0; j < 4; j++) {
                    int jp = j >> 1, jo = (j & 1) * 2;
                    MMA16816(acc[i][j], Af[i], (Wf[jp] + jo));
                }
            }
        }
    }

    // ---------------- epilogue ----------------
    #pragma unroll
    for (int i = 0; i < 4; i++) {
        int rb = m0 + wm * 64 + i * 16 + (lane >> 2);
        #pragma unroll
        for (int j = 0; j < 4; j++) {
            int col = n0 + wn * 32 + j * 8 + (lane & 3) * 2;
            float b0 = bias[col], b1 = bias[col + 1];
            #pragma unroll
            for (int half = 0; half < 2; half++) {
                int row = rb + half * 8;
                float o0 = acc[i][j][half * 2 + 0] + b0;
                float o1 = acc[i][j][half * 2 + 1] + b1;
                if (EPI == EPI_QKV) {
                    int b = row >> 11, t = row & 2047;
                    if (col < 512) {
                        int h = col >> 6, d = col & 63;
                        size_t ob = ((size_t)(b * 8 + h) * 2048 + t) * 64 + d;
                        cvtH2(o0 * 0.125f, o1 * 0.125f, Ch + ob);
                    } else if (col < 1024) {
                        int c = col - 512;
                        int h = c >> 6, d = c & 63;
                        size_t ob = ((size_t)(b * 8 + h) * 2048 + t) * 64 + d;
                        cvtH2(o0, o1, Kh + ob);
                    } else {
                        int c = col - 1024;
                        int h = c >> 6, d = c & 63;
                        size_t ob = ((size_t)(b * 8 + h) * 64 + d) * 2048 + t;
                        Vth[ob]        = __float2half_rn(o0);
                        Vth[ob + 2048] = __float2half_rn(o1);
                    }
                    continue;
                }
                size_t ob = (size_t)row * N + col;
                if (EPI == EPI_BIAS_RES) {
                    float2 rv = *(const float2*)(res + ob);
                    o0 += rv.x; o1 += rv.y;
                    float2 o = make_float2(o0, o1);
                    *(float2*)(Cf + ob) = o;
                }
                if (EPI == EPI_GELU) {
                    o0 = 0.5f * o0 * (1.0f + erff(o0 * 0.70710678118654752f));
                    o1 = 0.5f * o1 * (1.0f + erff(o1 * 0.70710678118654752f));
                    cvtH2(o0, o1, Ch + ob);
                }
            }
        }
    }
}

// ---------------- mma attention (all single fp16; P written in place over S) ----------------
// block = (qtile 64, bh). keys = 192. 256 threads / 8 warps. smem 62.7KB -> 3 CTAs/SM.
#define AQ     0u          // Q: 64 x 144
#define AK     9216u       // K: 192 x 144
#define AV     36864u      // VT: 64 x 400
#define AS     0u          // S->P fp16: 64 x 400 (overlays dead Q + K rows after phase 1)
#define ASUM   62464u
#define ATT_SMEM 62720u

__global__ __launch_bounds__(256)
void attn_mma(const h16* __restrict__ qq, const h16* __restrict__ kk,
              const h16* __restrict__ vt, h16* __restrict__ ctx) {
    extern __shared__ char sm[];
    const uint32_t sb = smem_u32(sm);
    const int tid = threadIdx.x;
    const int lane = tid & 31, wid = tid >> 5;
    const int bh = blockIdx.y;
    const int t0 = blockIdx.x * 64;
    const int kbase = t0 - 128;

    // ---- loads ----
    {
        #pragma unroll
        for (int it = 0; it < 2; it++) {
            int idx = tid + it * 256;
            int r = idx >> 3, c = idx & 7;
            cp16(sb + AQ + r * 144 + c * 16, qq + ((size_t)bh * 2048 + t0 + r) * 64 + c * 8);
        }
        #pragma unroll
        for (int it = 0; it < 6; it++) {
            int idx = tid + it * 256;
            int r = idx >> 3, c = idx & 7;
            int s = kbase + r;
            uint32_t sz = (s >= 0) ? 16u : 0u;
            int sc = s < 0 ? 0 : s;
            cp16z(sb + AK + r * 144 + c * 16, kk + ((size_t)bh * 2048 + sc) * 64 + c * 8, sz);
        }
        #pragma unroll
        for (int it = 0; it < 6; it++) {
            int idx = tid + it * 256;
            int r = idx / 24, c = idx - r * 24;
            int scol = kbase + c * 8;
            uint32_t sz = (scol >= 0) ? 16u : 0u;
            int sc = scol < 0 ? 0 : scol;
            cp16z(sb + AV + r * 400 + c * 16, vt + ((size_t)bh * 64 + r) * 2048 + sc, sz);
        }
    }
    CP_COMMIT();
    CP_WAIT(0);
    __syncthreads();

    // ---- phase 1: S = Q @ K^T ----
    const int mt = wid & 3;
    const int nh = wid >> 2;
    float Sacc[12][4];
    #pragma unroll
    for (int j = 0; j < 12; j++)
        #pragma unroll
        for (int r = 0; r < 4; r++) Sacc[j][r] = 0.0f;

    const uint32_t aOffBase = (mt * 16 + (lane & 15)) * 144;
    const uint32_t aHalf = (lane >> 4);
    const uint32_t bRowOff = (lane & 7) + ((lane >> 4) << 3);
    const uint32_t bHalf = (lane >> 3) & 1;

    #pragma unroll
    for (int kc = 0; kc < 4; kc++) {
        uint32_t ah[4];
        LDSM4(ah, sb + AQ + aOffBase + (kc * 2 + aHalf) * 16);
        #pragma unroll
        for (int jp = 0; jp < 6; jp++) {
            uint32_t bf[4];
            uint32_t boff = (nh * 96 + jp * 16 + bRowOff) * 144 + (kc * 2 + bHalf) * 16;
            LDSM4(bf, sb + AK + boff);
            #pragma unroll
            for (int jj = 0; jj < 2; jj++) {
                int j = jp * 2 + jj, jo = jj * 2;
                MMA16816(Sacc[j], ah, (bf + jo));
            }
        }
    }
    __syncthreads();   // Q and K reads done -> S may overlay them

    // write S (fp16) into overlay buffer
    {
        int r0 = mt * 16 + (lane >> 2);
        #pragma unroll
        for (int j = 0; j < 12; j++) {
            int cc = nh * 96 + j * 8 + (lane & 3) * 2;
            cvtH2(Sacc[j][0], Sacc[j][1], (h16*)(sm + AS + r0 * 400 + cc * 2));
            cvtH2(Sacc[j][2], Sacc[j][3], (h16*)(sm + AS + (r0 + 8) * 400 + cc * 2));
        }
    }
    __syncthreads();

    // ---- phase 2: softmax (P written in place over S) ----
    {
        int r = tid >> 2, tg = tid & 3;
        const h16* Sp = (const h16*)(sm + AS + r * 400);
        h16* Pp = (h16*)(sm + AS + r * 400);
        int jlo = r + 1;
        if (kbase < 0 && jlo < -kbase) jlo = -kbase;
        int jhi = r + 128;
        float mx = -1e30f;
        #pragma unroll 8
        for (int j2 = 0; j2 < 48; j2++) {
            int j = tg * 48 + j2;
            float v = __half2float(Sp[j]);
            bool ok = (j >= jlo) && (j <= jhi);
            mx = fmaxf(mx, ok ? v : -1e30f);
        }
        mx = fmaxf(mx, __shfl_xor_sync(0xffffffffu, mx, 1));
        mx = fmaxf(mx, __shfl_xor_sync(0xffffffffu, mx, 2));
        float sum = 0.0f;
        #pragma unroll 4
        for (int j2 = 0; j2 < 48; j2 += 2) {
            int j = tg * 48 + j2;
            float v0 = __half2float(Sp[j]), v1 = __half2float(Sp[j + 1]);
            bool ok0 = (j >= jlo) && (j <= jhi);
            bool ok1 = (j + 1 >= jlo) && (j + 1 <= jhi);
            float p0 = ok0 ? __expf(v0 - mx) : 0.0f;
            float p1 = ok1 ? __expf(v1 - mx) : 0.0f;
            sum += p0 + p1;
            cvtH2(p0, p1, Pp + j);
        }
        sum += __shfl_xor_sync(0xffffffffu, sum, 1);
        sum += __shfl_xor_sync(0xffffffffu, sum, 2);
        if (tg == 0) *(float*)(sm + ASUM + r * 4) = sum;
    }
    __syncthreads();

    // ---- phase 3: ctx = P @ V ----
    const int dh = wid >> 2;
    float Cacc[4][4];
    #pragma unroll
    for (int j = 0; j < 4; j++)
        #pragma unroll
        for (int r = 0; r < 4; r++) Cacc[j][r] = 0.0f;

    const uint32_t pOffBase = (mt * 16 + (lane & 15)) * 400;
    #pragma unroll
    for (int kc = 0; kc < 12; kc++) {
        uint32_t pa[4];
        LDSM4(pa, sb + AS + pOffBase + (kc * 2 + aHalf) * 16);
        #pragma unroll
        for (int jp = 0; jp < 2; jp++) {
            uint32_t vb[4];
            uint32_t voff = (dh * 32 + jp * 16 + bRowOff) * 400 + (kc * 2 + bHalf) * 16;
            LDSM4(vb, sb + AV + voff);
            #pragma unroll
            for (int jj = 0; jj < 2; jj++) {
                int j = jp * 2 + jj, jo = jj * 2;
                MMA16816(Cacc[j], pa, (vb + jo));
            }
        }
    }

    // epilogue
    {
        int b = bh >> 3, h = bh & 7;
        int rl0 = mt * 16 + (lane >> 2);
        float inv0 = 1.0f / *(const float*)(sm + ASUM + rl0 * 4);
        float inv1 = 1.0f / *(const float*)(sm + ASUM + (rl0 + 8) * 4);
        #pragma unroll
        for (int j = 0; j < 4; j++) {
            int d = dh * 32 + j * 8 + (lane & 3) * 2;
            size_t ob0 = ((size_t)(b * 2048 + t0 + rl0)) * 512 + h * 64 + d;
            size_t ob1 = ob0 + (size_t)8 * 512;
            cvtH2(Cacc[j][0] * inv0, Cacc[j][1] * inv0, ctx + ob0);
            cvtH2(Cacc[j][2] * inv1, Cacc[j][3] * inv1, ctx + ob1);
        }
    }
}

// ---------------- launch ----------------
extern "C" void kernel_launch(void* const* d_in, const int* in_sizes, int n_in,
                              void* d_out, int out_size) {
    const float* x     = (const float*)d_in[0];
    const float* in_w  = (const float*)d_in[1];
    const float* in_b  = (const float*)d_in[2];
    const float* out_w = (const float*)d_in[3];
    const float* out_b = (const float*)d_in[4];
    const float* ln1_g = (const float*)d_in[5];
    const float* ln1_b = (const float*)d_in[6];
    const float* ln2_g = (const float*)d_in[7];
    const float* ln2_b = (const float*)d_in[8];
    const float* w1    = (const float*)d_in[9];
    const float* b1    = (const float*)d_in[10];
    const float* w2    = (const float*)d_in[11];
    const float* b2    = (const float*)d_in[12];
    float* out = (float*)d_out;

    h16 *pq, *pk, *pvt, *px2, *pctx, *px3, *ph;
    h16 *pwa, *pwb, *pw1, *pw2;
    cudaGetSymbolAddress((void**)&pq, g_q);      cudaGetSymbolAddress((void**)&pk, g_k);
    cudaGetSymbolAddress((void**)&pvt, g_vt);
    cudaGetSymbolAddress((void**)&px2, g_x2);    cudaGetSymbolAddress((void**)&pctx, g_ctx);
    cudaGetSymbolAddress((void**)&px3, g_x3);    cudaGetSymbolAddress((void**)&ph, g_h);
    cudaGetSymbolAddress((void**)&pwa, g_wa);    cudaGetSymbolAddress((void**)&pwb, g_wb);
    cudaGetSymbolAddress((void**)&pw1, g_w1);    cudaGetSymbolAddress((void**)&pw2, g_w2);

    cudaFuncSetAttribute(gemm_mma<EPI_BIAS_RES>, cudaFuncAttributeMaxDynamicSharedMemorySize, GEMM_SMEM);
    cudaFuncSetAttribute(gemm_mma<EPI_GELU>,     cudaFuncAttributeMaxDynamicSharedMemorySize, GEMM_SMEM);
    cudaFuncSetAttribute(gemm_mma<EPI_QKV>,      cudaFuncAttributeMaxDynamicSharedMemorySize, GEMM_SMEM);
    cudaFuncSetAttribute(attn_mma, cudaFuncAttributeMaxDynamicSharedMemorySize, ATT_SMEM);

    // 0) weights -> fp16
    split_all_kernel<<<3072, 256>>>(in_w, out_w, w1, w2, pwa, pwb, pw1, pw2);

    // 1) x2 = LN1(x)
    ln_h_kernel<<<8192, 128>>>(x, ln1_g, ln1_b, px2);

    // 2) qkv projection -> q (scaled), k, v-transposed
    {
        dim3 grid(1536 / 128, 8192 / 128);
        gemm_mma<EPI_QKV><<<grid, 256, GEMM_SMEM>>>(px2, pwa, in_b, nullptr,
                                                    nullptr, pq, pk, pvt, 1536, 512);
    }

    // 3) ctx = sliding-window attention
    {
        dim3 grid(2048 / 64, 32);
        attn_mma<<<grid, 256, ATT_SMEM>>>(pq, pk, pvt, pctx);
    }

    // 4) out = x + ctx @ out_w^T + out_b
    {
        dim3 grid(512 / 128, 8192 / 128);
        gemm_mma<EPI_BIAS_RES><<<grid, 256, GEMM_SMEM>>>(pctx, pwb, out_b, x,
                                                         out, nullptr, nullptr, nullptr,
                                                         512, 512);
    }

    // 5) x3 = LN2(out)
    ln_h_kernel<<<8192, 128>>>(out, ln2_g, ln2_b, px3);

    // 6) h = gelu(x3 @ w1^T + b1)
    {
        dim3 grid(2048 / 128, 8192 / 128);
        gemm_mma<EPI_GELU><<<grid, 256, GEMM_SMEM>>>(px3, pw1, b1, nullptr,
                                                     nullptr, ph, nullptr, nullptr,
                                                     2048, 512);
    }

    // 7) out = out + h @ w2^T + b2
    {
        dim3 grid(512 / 128, 8192 / 128);
        gemm_mma<EPI_BIAS_RES><<<grid, 256, GEMM_SMEM>>>(ph, pw2, b2, out,
                                                         out, nullptr, nullptr, nullptr,
                                                         512, 2048);
    }
}

// round 16
// speedup vs baseline: 1.0389x; 1.0389x over previous
#include <cuda_runtime.h>
#include <cuda_fp16.h>
#include <math.h>
#include <stdint.h>

typedef __half h16;

// B=4, T=2048, D=512, H=8, HD=64, F=2048, WINDOW=128, rows=8192

// ---------------- scratch ----------------
__device__ h16  g_q  [32 * 2048 * 64];   // [bh][t][d], scaled
__device__ h16  g_k  [32 * 2048 * 64];   // [bh][t][d]
__device__ h16  g_vt [32 * 64 * 2048];   // [bh][d][t]
__device__ h16  g_x2 [8192 * 512];
__device__ h16  g_ctx[8192 * 512];
__device__ h16  g_x3 [8192 * 512];
__device__ h16  g_h  [8192 * 2048];
__device__ h16  g_wa [1536 * 512];
__device__ h16  g_wb [512 * 512];
__device__ h16  g_w1 [2048 * 512];
__device__ h16  g_w2 [512 * 2048];

// ---------------- helpers ----------------
__device__ __forceinline__ uint32_t smem_u32(const void* p) {
    uint32_t a;
    asm("{ .reg .u64 t; cvta.to.shared.u64 t, %1; cvt.u32.u64 %0, t; }" : "=r"(a) : "l"(p));
    return a;
}
__device__ __forceinline__ void cp16(uint32_t d, const void* g) {
    asm volatile("cp.async.cg.shared.global [%0], [%1], 16;" :: "r"(d), "l"(g));
}
__device__ __forceinline__ void cp16z(uint32_t d, const void* g, uint32_t srcsz) {
    asm volatile("cp.async.cg.shared.global [%0], [%1], 16, %2;" :: "r"(d), "l"(g), "r"(srcsz));
}
#define CP_COMMIT() asm volatile("cp.async.commit_group;" ::: "memory")
#define CP_WAIT(n)  asm volatile("cp.async.wait_group %0;" :: "n"(n) : "memory")

#define LDSM4(r, addr) \
    asm volatile("ldmatrix.sync.aligned.m8n8.x4.shared.b16 {%0,%1,%2,%3}, [%4];" \
        : "=r"((r)[0]), "=r"((r)[1]), "=r"((r)[2]), "=r"((r)[3]) : "r"(addr))

#define MMA16816(c, a, b) \
    asm volatile("mma.sync.aligned.m16n8k16.row.col.f32.f16.f16.f32 " \
        "{%0,%1,%2,%3}, {%4,%5,%6,%7}, {%8,%9}, {%0,%1,%2,%3};" \
        : "+f"((c)[0]), "+f"((c)[1]), "+f"((c)[2]), "+f"((c)[3]) \
        : "r"((a)[0]), "r"((a)[1]), "r"((a)[2]), "r"((a)[3]), "r"((b)[0]), "r"((b)[1]))

__device__ __forceinline__ void cvtH2(float a, float b, h16* p) {
    *(__half2*)p = __halves2half2(__float2half_rn(a), __float2half_rn(b));
}

// ---------------- fused prep: LN1 (blocks 0..8191) + weight convert (blocks 8192..14335) ----------------
__global__ void prep_kernel(const float* __restrict__ x, const float* __restrict__ gw,
                            const float* __restrict__ bw, h16* __restrict__ x2,
                            const float* __restrict__ in_w, const float* __restrict__ out_w,
                            const float* __restrict__ w1, const float* __restrict__ w2,
                            h16* __restrict__ wa, h16* __restrict__ wb,
                            h16* __restrict__ w1o, h16* __restrict__ w2o) {
    int t = threadIdx.x;
    if (blockIdx.x >= 8192) {
        // weight convert: unit = 4 floats; 786432 units over 6144 blocks x 128 threads
        int i = (blockIdx.x - 8192) * 128 + t;
        const float* src; h16* dst; int off;
        if (i < 196608)      { src = in_w;  dst = wa;  off = i; }
        else if (i < 262144) { src = out_w; dst = wb;  off = i - 196608; }
        else if (i < 524288) { src = w1;    dst = w1o; off = i - 262144; }
        else                 { src = w2;    dst = w2o; off = i - 524288; }
        float4 v = *(const float4*)(src + (size_t)off * 4);
        cvtH2(v.x, v.y, dst + (size_t)off * 4);
        cvtH2(v.z, v.w, dst + (size_t)off * 4 + 2);
        return;
    }
    // LN1 row
    int row = blockIdx.x;
    const float* xr = x + (size_t)row * 512;
    float4 v = *(const float4*)(xr + t * 4);
    float s  = v.x + v.y + v.z + v.w;
    float sq = v.x * v.x + v.y * v.y + v.z * v.z + v.w * v.w;
    #pragma unroll
    for (int of = 16; of > 0; of >>= 1) {
        s  += __shfl_xor_sync(0xffffffffu, s,  of);
        sq += __shfl_xor_sync(0xffffffffu, sq, of);
    }
    __shared__ float red[8];
    int wid = t >> 5, lane = t & 31;
    if (lane == 0) { red[wid] = s; red[4 + wid] = sq; }
    __syncthreads();
    float S  = red[0] + red[1] + red[2] + red[3];
    float SQ = red[4] + red[5] + red[6] + red[7];
    float mu   = S * (1.0f / 512.0f);
    float var  = SQ * (1.0f / 512.0f) - mu * mu;
    float rstd = rsqrtf(var + 1e-5f);
    float4 gv = *(const float4*)(gw + t * 4);
    float4 bv = *(const float4*)(bw + t * 4);
    float o0 = (v.x - mu) * rstd * gv.x + bv.x;
    float o1 = (v.y - mu) * rstd * gv.y + bv.y;
    float o2 = (v.z - mu) * rstd * gv.z + bv.z;
    float o3 = (v.w - mu) * rstd * gv.w + bv.w;
    size_t base = (size_t)row * 512 + t * 4;
    cvtH2(o0, o1, x2 + base);
    cvtH2(o2, o3, x2 + base + 2);
}

// ---------------- LayerNorm -> single fp16 ----------------
__global__ void ln_h_kernel(const float* __restrict__ x, const float* __restrict__ gw,
                            const float* __restrict__ bw, h16* __restrict__ o) {
    int row = blockIdx.x;
    int t = threadIdx.x;
    const float* xr = x + (size_t)row * 512;
    float4 v = *(const float4*)(xr + t * 4);
    float s  = v.x + v.y + v.z + v.w;
    float sq = v.x * v.x + v.y * v.y + v.z * v.z + v.w * v.w;
    #pragma unroll
    for (int of = 16; of > 0; of >>= 1) {
        s  += __shfl_xor_sync(0xffffffffu, s,  of);
        sq += __shfl_xor_sync(0xffffffffu, sq, of);
    }
    __shared__ float red[8];
    int wid = t >> 5, lane = t & 31;
    if (lane == 0) { red[wid] = s; red[4 + wid] = sq; }
    __syncthreads();
    float S  = red[0] + red[1] + red[2] + red[3];
    float SQ = red[4] + red[5] + red[6] + red[7];
    float mu   = S * (1.0f / 512.0f);
    float var  = SQ * (1.0f / 512.0f) - mu * mu;
    float rstd = rsqrtf(var + 1e-5f);
    float4 gv = *(const float4*)(gw + t * 4);
    float4 bv = *(const float4*)(bw + t * 4);
    float o0 = (v.x - mu) * rstd * gv.x + bv.x;
    float o1 = (v.y - mu) * rstd * gv.y + bv.y;
    float o2 = (v.z - mu) * rstd * gv.z + bv.z;
    float o3 = (v.w - mu) * rstd * gv.w + bv.w;
    size_t base = (size_t)row * 512 + t * 4;
    cvtH2(o0, o1, o + base);
    cvtH2(o2, o3, o + base + 2);
}

// ---------------- mma.sync GEMM (R11 config): CTA 128x128, 4 warps 64x64, BK=32, 4-stage ----------------
#define EPI_BIAS_RES   1
#define EPI_GELU       2
#define EPI_QKV        3

#define TILE_B   8192            // 128 rows x 64 B
#define STAGE_B  (2 * TILE_B)    // 16384 (A, W)
#define NSTAGE   4
#define GEMM_SMEM (NSTAGE * STAGE_B)   // 65536

#define SWIZ(row, chunk) ((row) * 64 + (((chunk) ^ (((row) >> 1) & 3)) << 4))

template<int EPI>
__global__ __launch_bounds__(128)
void gemm_mma(const h16* __restrict__ A, const h16* __restrict__ W,
              const float* __restrict__ bias, const float* __restrict__ res,
              float* __restrict__ Cf, h16* __restrict__ Ch,
              h16* __restrict__ Kh, h16* __restrict__ Vth,
              int N, int K) {
    extern __shared__ char sm[];
    const int tid = threadIdx.x;
    const int lane = tid & 31, wid = tid >> 5;
    const int wm = wid & 1, wn = wid >> 1;
    const int m0 = blockIdx.y * 128, n0 = blockIdx.x * 128;
    const uint32_t sbase = smem_u32(sm);

    const h16* srcs[2] = { A + (size_t)m0 * K, W + (size_t)n0 * K };

    auto load_stage = [&](int s, int kb) {
        uint32_t so = sbase + (uint32_t)s * STAGE_B;
        #pragma unroll
        for (int tt = 0; tt < 2; tt++) {
            const h16* gp = srcs[tt] + kb * 32;
            uint32_t tb = so + tt * TILE_B;
            #pragma unroll
            for (int it = 0; it < 4; it++) {
                int idx = tid + it * 128;          // 0..511
                int r = idx >> 2, c = idx & 3;
                cp16(tb + SWIZ(r, c), gp + (size_t)r * K + c * 8);
            }
        }
    };

    float acc[4][8][4];
    #pragma unroll
    for (int i = 0; i < 4; i++)
        #pragma unroll
        for (int j = 0; j < 8; j++)
            #pragma unroll
            for (int r = 0; r < 4; r++) acc[i][j][r] = 0.0f;

    const int nkb = K >> 5;

    load_stage(0, 0); CP_COMMIT();
    load_stage(1, 1); CP_COMMIT();
    load_stage(2, 2); CP_COMMIT();

    const uint32_t aRow = wm * 64 + (lane & 15);
    const uint32_t aChunkHalf = (lane >> 4);
    const uint32_t bRow = wn * 64 + (lane & 7) + ((lane >> 4) << 3);
    const uint32_t bChunkHalf = (lane >> 3) & 1;

    for (int kb = 0; kb < nkb; kb++) {
        bool more = (kb + NSTAGE - 1) < nkb;
        if (more) { CP_WAIT(NSTAGE - 2); } else { CP_WAIT(0); }
        __syncthreads();
        if (more) { load_stage((kb + NSTAGE - 1) % NSTAGE, kb + NSTAGE - 1); CP_COMMIT(); }

        uint32_t so = sbase + (uint32_t)(kb % NSTAGE) * STAGE_B;
        #pragma unroll
        for (int ks = 0; ks < 2; ks++) {
            const uint32_t kcA = ks * 2 + aChunkHalf;
            const uint32_t kcB = ks * 2 + bChunkHalf;
            uint32_t Af[4][4];
            #pragma unroll
            for (int i = 0; i < 4; i++)
                LDSM4(Af[i], so + SWIZ(aRow + i * 16, kcA));
            uint32_t Wf[4][4];
            #pragma unroll
            for (int jp = 0; jp < 4; jp++)
                LDSM4(Wf[jp], so + TILE_B + SWIZ(bRow + jp * 16, kcB));
            #pragma unroll
            for (int i = 0; i < 4; i++) {
                #pragma unroll
                for (int j = 0; j < 8; j++) {
                    int jp = j >> 1, jo = (j & 1) * 2;
                    MMA16816(acc[i][j], Af[i], (Wf[jp] + jo));
                }
            }
        }
    }

    // ---------------- epilogue ----------------
    #pragma unroll
    for (int i = 0; i < 4; i++) {
        int rb = m0 + wm * 64 + i * 16 + (lane >> 2);
        #pragma unroll
        for (int j = 0; j < 8; j++) {
            int col = n0 + wn * 64 + j * 8 + (lane & 3) * 2;
            float b0 = bias[col], b1 = bias[col + 1];
            #pragma unroll
            for (int half = 0; half < 2; half++) {
                int row = rb + half * 8;
                float o0 = acc[i][j][half * 2 + 0] + b0;
                float o1 = acc[i][j][half * 2 + 1] + b1;
                if (EPI == EPI_QKV) {
                    int b = row >> 11, t = row & 2047;
                    if (col < 512) {
                        int h = col >> 6, d = col & 63;
                        size_t ob = ((size_t)(b * 8 + h) * 2048 + t) * 64 + d;
                        cvtH2(o0 * 0.125f, o1 * 0.125f, Ch + ob);
                    } else if (col < 1024) {
                        int c = col - 512;
                        int h = c >> 6, d = c & 63;
                        size_t ob = ((size_t)(b * 8 + h) * 2048 + t) * 64 + d;
                        cvtH2(o0, o1, Kh + ob);
                    } else {
                        int c = col - 1024;
                        int h = c >> 6, d = c & 63;
                        size_t ob = ((size_t)(b * 8 + h) * 64 + d) * 2048 + t;
                        Vth[ob]        = __float2half_rn(o0);
                        Vth[ob + 2048] = __float2half_rn(o1);
                    }
                    continue;
                }
                size_t ob = (size_t)row * N + col;
                if (EPI == EPI_BIAS_RES) {
                    float2 rv = *(const float2*)(res + ob);
                    o0 += rv.x; o1 += rv.y;
                    float2 o = make_float2(o0, o1);
                    *(float2*)(Cf + ob) = o;
                }
                if (EPI == EPI_GELU) {
                    o0 = 0.5f * o0 * (1.0f + erff(o0 * 0.70710678118654752f));
                    o1 = 0.5f * o1 * (1.0f + erff(o1 * 0.70710678118654752f));
                    cvtH2(o0, o1, Ch + ob);
                }
            }
        }
    }
}

// ---------------- mma attention (R14 config: P in place over S, 62.7KB, 3 CTAs/SM) ----------------
#define AQ     0u          // Q: 64 x 144
#define AK     9216u       // K: 192 x 144
#define AV     36864u      // VT: 64 x 400
#define AS     0u          // S->P fp16: 64 x 400 (overlays dead Q + K rows after phase 1)
#define ASUM   62464u
#define ATT_SMEM 62720u

__global__ __launch_bounds__(256)
void attn_mma(const h16* __restrict__ qq, const h16* __restrict__ kk,
              const h16* __restrict__ vt, h16* __restrict__ ctx) {
    extern __shared__ char sm[];
    const uint32_t sb = smem_u32(sm);
    const int tid = threadIdx.x;
    const int lane = tid & 31, wid = tid >> 5;
    const int bh = blockIdx.y;
    const int t0 = blockIdx.x * 64;
    const int kbase = t0 - 128;

    // ---- loads ----
    {
        #pragma unroll
        for (int it = 0; it < 2; it++) {
            int idx = tid + it * 256;
            int r = idx >> 3, c = idx & 7;
            cp16(sb + AQ + r * 144 + c * 16, qq + ((size_t)bh * 2048 + t0 + r) * 64 + c * 8);
        }
        #pragma unroll
        for (int it = 0; it < 6; it++) {
            int idx = tid + it * 256;
            int r = idx >> 3, c = idx & 7;
            int s = kbase + r;
            uint32_t sz = (s >= 0) ? 16u : 0u;
            int sc = s < 0 ? 0 : s;
            cp16z(sb + AK + r * 144 + c * 16, kk + ((size_t)bh * 2048 + sc) * 64 + c * 8, sz);
        }
        #pragma unroll
        for (int it = 0; it < 6; it++) {
            int idx = tid + it * 256;
            int r = idx / 24, c = idx - r * 24;
            int scol = kbase + c * 8;
            uint32_t sz = (scol >= 0) ? 16u : 0u;
            int sc = scol < 0 ? 0 : scol;
            cp16z(sb + AV + r * 400 + c * 16, vt + ((size_t)bh * 64 + r) * 2048 + sc, sz);
        }
    }
    CP_COMMIT();
    CP_WAIT(0);
    __syncthreads();

    // ---- phase 1: S = Q @ K^T ----
    const int mt = wid & 3;
    const int nh = wid >> 2;
    float Sacc[12][4];
    #pragma unroll
    for (int j = 0; j < 12; j++)
        #pragma unroll
        for (int r = 0; r < 4; r++) Sacc[j][r] = 0.0f;

    const uint32_t aOffBase = (mt * 16 + (lane & 15)) * 144;
    const uint32_t aHalf = (lane >> 4);
    const uint32_t bRowOff = (lane & 7) + ((lane >> 4) << 3);
    const uint32_t bHalf = (lane >> 3) & 1;

    #pragma unroll
    for (int kc = 0; kc < 4; kc++) {
        uint32_t ah[4];
        LDSM4(ah, sb + AQ + aOffBase + (kc * 2 + aHalf) * 16);
        #pragma unroll
        for (int jp = 0; jp < 6; jp++) {
            uint32_t bf[4];
            uint32_t boff = (nh * 96 + jp * 16 + bRowOff) * 144 + (kc * 2 + bHalf) * 16;
            LDSM4(bf, sb + AK + boff);
            #pragma unroll
            for (int jj = 0; jj < 2; jj++) {
                int j = jp * 2 + jj, jo = jj * 2;
                MMA16816(Sacc[j], ah, (bf + jo));
            }
        }
    }
    __syncthreads();   // Q and K reads done -> S may overlay them

    // write S (fp16) into overlay buffer
    {
        int r0 = mt * 16 + (lane >> 2);
        #pragma unroll
        for (int j = 0; j < 12; j++) {
            int cc = nh * 96 + j * 8 + (lane & 3) * 2;
            cvtH2(Sacc[j][0], Sacc[j][1], (h16*)(sm + AS + r0 * 400 + cc * 2));
            cvtH2(Sacc[j][2], Sacc[j][3], (h16*)(sm + AS + (r0 + 8) * 400 + cc * 2));
        }
    }
    __syncthreads();

    // ---- phase 2: softmax (P written in place over S) ----
    {
        int r = tid >> 2, tg = tid & 3;
        const h16* Sp = (const h16*)(sm + AS + r * 400);
        h16* Pp = (h16*)(sm + AS + r * 400);
        int jlo = r + 1;
        if (kbase < 0 && jlo < -kbase) jlo = -kbase;
        int jhi = r + 128;
        float mx = -1e30f;
        #pragma unroll 8
        for (int j2 = 0; j2 < 48; j2++) {
            int j = tg * 48 + j2;
            float v = __half2float(Sp[j]);
            bool ok = (j >= jlo) && (j <= jhi);
            mx = fmaxf(mx, ok ? v : -1e30f);
        }
        mx = fmaxf(mx, __shfl_xor_sync(0xffffffffu, mx, 1));
        mx = fmaxf(mx, __shfl_xor_sync(0xffffffffu, mx, 2));
        float sum = 0.0f;
        #pragma unroll 4
        for (int j2 = 0; j2 < 48; j2 += 2) {
            int j = tg * 48 + j2;
            float v0 = __half2float(Sp[j]), v1 = __half2float(Sp[j + 1]);
            bool ok0 = (j >= jlo) && (j <= jhi);
            bool ok1 = (j + 1 >= jlo) && (j + 1 <= jhi);
            float p0 = ok0 ? __expf(v0 - mx) : 0.0f;
            float p1 = ok1 ? __expf(v1 - mx) : 0.0f;
            sum += p0 + p1;
            cvtH2(p0, p1, Pp + j);
        }
        sum += __shfl_xor_sync(0xffffffffu, sum, 1);
        sum += __shfl_xor_sync(0xffffffffu, sum, 2);
        if (tg == 0) *(float*)(sm + ASUM + r * 4) = sum;
    }
    __syncthreads();

    // ---- phase 3: ctx = P @ V ----
    const int dh = wid >> 2;
    float Cacc[4][4];
    #pragma unroll
    for (int j = 0; j < 4; j++)
        #pragma unroll
        for (int r = 0; r < 4; r++) Cacc[j][r] = 0.0f;

    const uint32_t pOffBase = (mt * 16 + (lane & 15)) * 400;
    #pragma unroll
    for (int kc = 0; kc < 12; kc++) {
        uint32_t pa[4];
        LDSM4(pa, sb + AS + pOffBase + (kc * 2 + aHalf) * 16);
        #pragma unroll
        for (int jp = 0; jp < 2; jp++) {
            uint32_t vb[4];
            uint32_t voff = (dh * 32 + jp * 16 + bRowOff) * 400 + (kc * 2 + bHalf) * 16;
            LDSM4(vb, sb + AV + voff);
            #pragma unroll
            for (int jj = 0; jj < 2; jj++) {
                int j = jp * 2 + jj, jo = jj * 2;
                MMA16816(Cacc[j], pa, (vb + jo));
            }
        }
    }

    // epilogue
    {
        int b = bh >> 3, h = bh & 7;
        int rl0 = mt * 16 + (lane >> 2);
        float inv0 = 1.0f / *(const float*)(sm + ASUM + rl0 * 4);
        float inv1 = 1.0f / *(const float*)(sm + ASUM + (rl0 + 8) * 4);
        #pragma unroll
        for (int j = 0; j < 4; j++) {
            int d = dh * 32 + j * 8 + (lane & 3) * 2;
            size_t ob0 = ((size_t)(b * 2048 + t0 + rl0)) * 512 + h * 64 + d;
            size_t ob1 = ob0 + (size_t)8 * 512;
            cvtH2(Cacc[j][0] * inv0, Cacc[j][1] * inv0, ctx + ob0);
            cvtH2(Cacc[j][2] * inv1, Cacc[j][3] * inv1, ctx + ob1);
        }
    }
}

// ---------------- launch ----------------
extern "C" void kernel_launch(void* const* d_in, const int* in_sizes, int n_in,
                              void* d_out, int out_size) {
    const float* x     = (const float*)d_in[0];
    const float* in_w  = (const float*)d_in[1];
    const float* in_b  = (const float*)d_in[2];
    const float* out_w = (const float*)d_in[3];
    const float* out_b = (const float*)d_in[4];
    const float* ln1_g = (const float*)d_in[5];
    const float* ln1_b = (const float*)d_in[6];
    const float* ln2_g = (const float*)d_in[7];
    const float* ln2_b = (const float*)d_in[8];
    const float* w1    = (const float*)d_in[9];
    const float* b1    = (const float*)d_in[10];
    const float* w2    = (const float*)d_in[11];
    const float* b2    = (const float*)d_in[12];
    float* out = (float*)d_out;

    h16 *pq, *pk, *pvt, *px2, *pctx, *px3, *ph;
    h16 *pwa, *pwb, *pw1, *pw2;
    cudaGetSymbolAddress((void**)&pq, g_q);      cudaGetSymbolAddress((void**)&pk, g_k);
    cudaGetSymbolAddress((void**)&pvt, g_vt);
    cudaGetSymbolAddress((void**)&px2, g_x2);    cudaGetSymbolAddress((void**)&pctx, g_ctx);
    cudaGetSymbolAddress((void**)&px3, g_x3);    cudaGetSymbolAddress((void**)&ph, g_h);
    cudaGetSymbolAddress((void**)&pwa, g_wa);    cudaGetSymbolAddress((void**)&pwb, g_wb);
    cudaGetSymbolAddress((void**)&pw1, g_w1);    cudaGetSymbolAddress((void**)&pw2, g_w2);

    cudaFuncSetAttribute(gemm_mma<EPI_BIAS_RES>, cudaFuncAttributeMaxDynamicSharedMemorySize, GEMM_SMEM);
    cudaFuncSetAttribute(gemm_mma<EPI_GELU>,     cudaFuncAttributeMaxDynamicSharedMemorySize, GEMM_SMEM);
    cudaFuncSetAttribute(gemm_mma<EPI_QKV>,      cudaFuncAttributeMaxDynamicSharedMemorySize, GEMM_SMEM);
    cudaFuncSetAttribute(attn_mma, cudaFuncAttributeMaxDynamicSharedMemorySize, ATT_SMEM);

    // 0+1) fused: LN1 (8192 blocks) + weight convert (6144 blocks)
    prep_kernel<<<8192 + 6144, 128>>>(x, ln1_g, ln1_b, px2,
                                      in_w, out_w, w1, w2, pwa, pwb, pw1, pw2);

    // 2) qkv projection -> q (scaled), k, v-transposed
    {
        dim3 grid(1536 / 128, 8192 / 128);
        gemm_mma<EPI_QKV><<<grid, 128, GEMM_SMEM>>>(px2, pwa, in_b, nullptr,
                                                    nullptr, pq, pk, pvt, 1536, 512);
    }

    // 3) ctx = sliding-window attention
    {
        dim3 grid(2048 / 64, 32);
        attn_mma<<<grid, 256, ATT_SMEM>>>(pq, pk, pvt, pctx);
    }

    // 4) out = x + ctx @ out_w^T + out_b
    {
        dim3 grid(512 / 128, 8192 / 128);
        gemm_mma<EPI_BIAS_RES><<<grid, 128, GEMM_SMEM>>>(pctx, pwb, out_b, x,
                                                         out, nullptr, nullptr, nullptr,
                                                         512, 512);
    }

    // 5) x3 = LN2(out)
    ln_h_kernel<<<8192, 128>>>(out, ln2_g, ln2_b, px3);

    // 6) h = gelu(x3 @ w1^T + b1)
    {
        dim3 grid(2048 / 128, 8192 / 128);
        gemm_mma<EPI_GELU><<<grid, 128, GEMM_SMEM>>>(px3, pw1, b1, nullptr,
                                                     nullptr, ph, nullptr, nullptr,
                                                     2048, 512);
    }

    // 7) out = out + h @ w2^T + b2
    {
        dim3 grid(512 / 128, 8192 / 128);
        gemm_mma<EPI_BIAS_RES><<<grid, 128, GEMM_SMEM>>>(ph, pw2, b2, out,
                                                         out, nullptr, nullptr, nullptr,
                                                         512, 2048);
    }
}